// round 2
// baseline (speedup 1.0000x reference)
#include <cuda_runtime.h>
#include <cuda_bf16.h>
#include <cstdint>

// ============================================================================
// ContraNorm: out = 1.1*x - 0.1 * softmax(xn @ xn^T) @ x,   N=16384, D=256
// Flash formulation, mma.sync (bf16, fp32 accum) — sm_103 baseline ISA only.
// ============================================================================

#define N_ROWS 16384
#define DIM    256
#define BM     128
#define BN     128
#define NTILES (N_ROWS / BN)

__device__ __align__(16) __nv_bfloat16 g_xn[(size_t)N_ROWS * DIM];  // normalized rows
__device__ __align__(16) __nv_bfloat16 g_xT[(size_t)DIM * N_ROWS];  // x^T in bf16

// ---------------------------------------------------------------------------
__device__ __forceinline__ uint32_t smem_to_u32(const void* p) {
    uint32_t a;
    asm("{ .reg .u64 t; cvta.to.shared.u64 t, %1; cvt.u32.u64 %0, t; }" : "=r"(a) : "l"(p));
    return a;
}

__device__ __forceinline__ void ldsm_x4(uint32_t (&r)[4], uint32_t addr) {
    asm volatile("ldmatrix.sync.aligned.m8n8.x4.shared.b16 {%0,%1,%2,%3}, [%4];"
        : "=r"(r[0]), "=r"(r[1]), "=r"(r[2]), "=r"(r[3]) : "r"(addr));
}

__device__ __forceinline__ void mma_bf16(float (&c)[4], const uint32_t (&a)[4],
                                         uint32_t b0, uint32_t b1) {
    asm volatile(
        "mma.sync.aligned.m16n8k16.row.col.f32.bf16.bf16.f32 "
        "{%0,%1,%2,%3}, {%4,%5,%6,%7}, {%8,%9}, {%0,%1,%2,%3};"
        : "+f"(c[0]), "+f"(c[1]), "+f"(c[2]), "+f"(c[3])
        : "r"(a[0]), "r"(a[1]), "r"(a[2]), "r"(a[3]), "r"(b0), "r"(b1));
}

#define STS128(r0, r1, r2, r3, smem_addr) \
    asm volatile("st.shared.v4.b32 [%0], {%1, %2, %3, %4};" \
        :: "r"(smem_addr), "r"(r0), "r"(r1), "r"(r2), "r"(r3) : "memory")

#define STS32(smem_addr, v) \
    asm volatile("st.shared.b32 [%0], %1;" :: "r"(smem_addr), "r"(v) : "memory")

// pack two fp32 -> bf16x2 (lo = a, hi = b)
#define CVT_BF16X2_F32(result, a, b) \
    asm("cvt.rn.bf16x2.f32 %0, %1, %2;" : "=r"(result) : "f"(b), "f"(a))

// SMEM layout (bytes)
#define SQ 0            // Q tile  [128][256] bf16, row stride 512 B
#define SK 65536        // K tile  [128][256] bf16, row stride 512 B
#define SV 131072       // Vt tile [256][128] bf16, row stride 256 B
#define SP 196608       // P tile  [128][128] bf16, row stride 256 B
#define SMEM_TOTAL 229376

// ---------------------------------------------------------------------------
// Prologue 1: per-row L2 normalize, fp32 -> bf16 (row-major)
// ---------------------------------------------------------------------------
__global__ void normalize_kernel(const float* __restrict__ x) {
    int row  = blockIdx.x * 8 + (threadIdx.x >> 5);
    int lane = threadIdx.x & 31;
    const float4* xr = reinterpret_cast<const float4*>(x + (size_t)row * DIM);
    float4 a = xr[lane * 2];
    float4 b = xr[lane * 2 + 1];
    float ss = a.x*a.x + a.y*a.y + a.z*a.z + a.w*a.w
             + b.x*b.x + b.y*b.y + b.z*b.z + b.w*b.w;
    #pragma unroll
    for (int o = 16; o > 0; o >>= 1) ss += __shfl_xor_sync(0xFFFFFFFFu, ss, o);
    float inv = 1.0f / fmaxf(sqrtf(ss), 1e-12f);

    __nv_bfloat162 p0 = __floats2bfloat162_rn(a.x * inv, a.y * inv);
    __nv_bfloat162 p1 = __floats2bfloat162_rn(a.z * inv, a.w * inv);
    __nv_bfloat162 p2 = __floats2bfloat162_rn(b.x * inv, b.y * inv);
    __nv_bfloat162 p3 = __floats2bfloat162_rn(b.z * inv, b.w * inv);
    uint4 v;
    v.x = *reinterpret_cast<uint32_t*>(&p0);
    v.y = *reinterpret_cast<uint32_t*>(&p1);
    v.z = *reinterpret_cast<uint32_t*>(&p2);
    v.w = *reinterpret_cast<uint32_t*>(&p3);
    *reinterpret_cast<uint4*>(&g_xn[(size_t)row * DIM + lane * 8]) = v;
}

// ---------------------------------------------------------------------------
// Prologue 2: tiled transpose x (fp32, [N,D]) -> g_xT (bf16, [D,N])
// ---------------------------------------------------------------------------
__global__ void transpose_kernel(const float* __restrict__ x) {
    __shared__ float t[32][33];
    int i0 = blockIdx.x * 32;
    int d0 = blockIdx.y * 32;
    int lane = threadIdx.x & 31;
    int w    = threadIdx.x >> 5;   // 8 warps
    #pragma unroll
    for (int rr = w; rr < 32; rr += 8)
        t[rr][lane] = x[(size_t)(i0 + rr) * DIM + d0 + lane];
    __syncthreads();
    #pragma unroll
    for (int rr = w; rr < 32; rr += 8)
        g_xT[(size_t)(d0 + rr) * N_ROWS + i0 + lane] = __float2bfloat16(t[lane][rr]);
}

// ---------------------------------------------------------------------------
// Main flash kernel: 1 CTA per 128-row block, 512 threads (16 warps, 8x2)
// ---------------------------------------------------------------------------
__global__ void __launch_bounds__(512, 1)
contranorm_main(const float* __restrict__ x, float* __restrict__ out) {
    extern __shared__ __align__(1024) char smem[];
    const uint32_t sb = smem_to_u32(smem);
    const int tid  = threadIdx.x;
    const int lane = tid & 31;
    const int wid  = tid >> 5;
    const int wr   = wid >> 1;            // 0..7 row-warp
    const int wc   = wid & 1;             // 0..1 col-warp
    const int m0   = wr * 16;
    const int keybase = wc * 64;          // S col slice
    const int dimbase = wc * 128;         // O col slice
    const int r0   = blockIdx.x * BM;

    const int sub = lane >> 3;            // ldmatrix submatrix id
    const int li  = lane & 7;
    const uint32_t XR = (uint32_t)li << 4;  // swizzle term for ldmatrix rows

    // ---- thread-constant ldmatrix row bases ----
    // QK A (Q tile, stride 512): row = m0 + li + (sub&1)*8
    const uint32_t a_qk_base = sb + SQ + (uint32_t)(m0 + li + ((sub & 1) << 3)) * 512;
    const uint32_t a_qk_csel = (uint32_t)((sub >> 1) << 4);
    // QK B (K tile, stride 512): row = keybase + q*16 + li + (sub>>1)*8
    const uint32_t b_qk_base = sb + SK + (uint32_t)(keybase + li + ((sub >> 1) << 3)) * 512;
    const uint32_t b_qk_csel = (uint32_t)((sub & 1) << 4);
    // PV A (P tile, stride 256): row = m0 + li + (sub&1)*8
    const uint32_t a_pv_base = sb + SP + (uint32_t)(m0 + li + ((sub & 1) << 3)) * 256;
    // PV B (Vt tile, stride 256): row = dimbase + q*16 + li + (sub>>1)*8
    const uint32_t b_pv_base = sb + SV + (uint32_t)(dimbase + li + ((sub >> 1) << 3)) * 256;

    // P store addressing (per-thread constant parts)
    const int g4   = lane >> 2;           // 0..7
    const int q4   = lane & 3;            // 0..3
    const uint32_t XRp = (uint32_t)g4 << 4;
    const uint32_t p_st_lo = sb + SP + (uint32_t)(m0 + g4) * 256;
    const uint32_t p_st_hi = sb + SP + (uint32_t)(m0 + g4 + 8) * 256;

    // ---- load Q tile once: g_xn rows r0..r0+127, swizzled [128][256] ----
    {
        const __nv_bfloat16* src = g_xn + (size_t)r0 * DIM;
        #pragma unroll
        for (int it = 0; it < 8; it++) {
            int idx = tid + it * 512;          // 0..4095
            int row = idx >> 5;
            int c16 = idx & 31;
            uint4 v = *reinterpret_cast<const uint4*>(src + row * DIM + c16 * 8);
            uint32_t byte = (uint32_t)row * 512 + ((uint32_t)(c16 * 16) ^ ((row & 7) << 4));
            STS128(v.x, v.y, v.z, v.w, sb + SQ + byte);
        }
    }

    float oacc[16][4];
    #pragma unroll
    for (int t = 0; t < 16; t++)
        #pragma unroll
        for (int u = 0; u < 4; u++) oacc[t][u] = 0.0f;
    float dsum0 = 0.0f, dsum1 = 0.0f;

    for (int j = 0; j < NTILES; j++) {
        // ---- load K tile [128][256] and Vt tile [256][128] ----
        {
            const __nv_bfloat16* src = g_xn + (size_t)j * BN * DIM;
            #pragma unroll
            for (int it = 0; it < 8; it++) {
                int idx = tid + it * 512;
                int row = idx >> 5;
                int c16 = idx & 31;
                uint4 v = *reinterpret_cast<const uint4*>(src + row * DIM + c16 * 8);
                uint32_t byte = (uint32_t)row * 512 + ((uint32_t)(c16 * 16) ^ ((row & 7) << 4));
                STS128(v.x, v.y, v.z, v.w, sb + SK + byte);
            }
            const __nv_bfloat16* srcv = g_xT + (size_t)j * BN;
            #pragma unroll
            for (int it = 0; it < 8; it++) {
                int idx = tid + it * 512;          // 0..4095
                int row = idx >> 4;                // dim 0..255
                int c16 = idx & 15;
                uint4 v = *reinterpret_cast<const uint4*>(srcv + (size_t)row * N_ROWS + c16 * 8);
                uint32_t byte = (uint32_t)row * 256 + ((uint32_t)(c16 * 16) ^ ((row & 7) << 4));
                STS128(v.x, v.y, v.z, v.w, sb + SV + byte);
            }
        }
        __syncthreads();

        // ---- QK^T: S[16 x 64] per warp, K=256 ----
        float sacc[8][4];
        #pragma unroll
        for (int t = 0; t < 8; t++)
            #pragma unroll
            for (int u = 0; u < 4; u++) sacc[t][u] = 0.0f;

        #pragma unroll 4
        for (int kk = 0; kk < 16; kk++) {
            uint32_t colA = ((uint32_t)(kk << 5) | a_qk_csel) ^ XR;
            uint32_t a[4];
            ldsm_x4(a, a_qk_base + colA);
            uint32_t colB = ((uint32_t)(kk << 5) | b_qk_csel) ^ XR;
            #pragma unroll
            for (int q = 0; q < 4; q++) {
                uint32_t b[4];
                ldsm_x4(b, b_qk_base + (uint32_t)q * 8192 + colB);
                mma_bf16(sacc[2 * q],     a, b[0], b[1]);
                mma_bf16(sacc[2 * q + 1], a, b[2], b[3]);
            }
        }

        // ---- epilogue: exp, denom, P -> SMEM (bf16) ----
        #pragma unroll
        for (int nt = 0; nt < 8; nt++) {
            float e0 = __expf(sacc[nt][0]);
            float e1 = __expf(sacc[nt][1]);
            float e2 = __expf(sacc[nt][2]);
            float e3 = __expf(sacc[nt][3]);
            dsum0 += e0 + e1;
            dsum1 += e2 + e3;
            uint32_t plo, phi;
            CVT_BF16X2_F32(plo, e0, e1);
            CVT_BF16X2_F32(phi, e2, e3);
            uint32_t colb = (uint32_t)((keybase + nt * 8 + q4 * 2) * 2) ^ XRp;
            STS32(p_st_lo + colb, plo);
            STS32(p_st_hi + colb, phi);
        }
        __syncthreads();

        // ---- PV: O[16 x 128] per warp += P @ x_tile ----
        #pragma unroll 2
        for (int kk = 0; kk < 8; kk++) {
            uint32_t colA = ((uint32_t)(kk << 5) | a_qk_csel) ^ XR;   // same csel as A
            uint32_t a[4];
            ldsm_x4(a, a_pv_base + colA);
            uint32_t colB = ((uint32_t)(kk << 5) | b_qk_csel) ^ XR;
            #pragma unroll
            for (int q = 0; q < 8; q++) {
                uint32_t b[4];
                ldsm_x4(b, b_pv_base + (uint32_t)q * 4096 + colB);
                mma_bf16(oacc[2 * q],     a, b[0], b[1]);
                mma_bf16(oacc[2 * q + 1], a, b[2], b[3]);
            }
        }
        __syncthreads();
    }

    // ---- final blend: out = 1.1*x - (0.1/denom) * O ----
    {
        float d0 = dsum0, d1 = dsum1;
        d0 += __shfl_xor_sync(0xFFFFFFFFu, d0, 1);
        d0 += __shfl_xor_sync(0xFFFFFFFFu, d0, 2);
        d1 += __shfl_xor_sync(0xFFFFFFFFu, d1, 1);
        d1 += __shfl_xor_sync(0xFFFFFFFFu, d1, 2);
        float c0 = 0.1f / d0;
        float c1 = 0.1f / d1;
        int row_lo = r0 + m0 + g4;
        int row_hi = row_lo + 8;
        const float2* x_lo = reinterpret_cast<const float2*>(x + (size_t)row_lo * DIM);
        const float2* x_hi = reinterpret_cast<const float2*>(x + (size_t)row_hi * DIM);
        float2* o_lo = reinterpret_cast<float2*>(out + (size_t)row_lo * DIM);
        float2* o_hi = reinterpret_cast<float2*>(out + (size_t)row_hi * DIM);
        #pragma unroll
        for (int nt = 0; nt < 16; nt++) {
            int cidx = (dimbase + nt * 8 + q4 * 2) >> 1;
            float2 xv = x_lo[cidx];
            float2 ov;
            ov.x = 1.1f * xv.x - c0 * oacc[nt][0];
            ov.y = 1.1f * xv.y - c0 * oacc[nt][1];
            o_lo[cidx] = ov;
            float2 xw = x_hi[cidx];
            float2 ow;
            ow.x = 1.1f * xw.x - c1 * oacc[nt][2];
            ow.y = 1.1f * xw.y - c1 * oacc[nt][3];
            o_hi[cidx] = ow;
        }
    }
}

// ---------------------------------------------------------------------------
extern "C" void kernel_launch(void* const* d_in, const int* in_sizes, int n_in,
                              void* d_out, int out_size) {
    const float* x = (const float*)d_in[0];
    float* out = (float*)d_out;

    normalize_kernel<<<N_ROWS / 8, 256>>>(x);
    transpose_kernel<<<dim3(N_ROWS / 32, DIM / 32), 256>>>(x);

    cudaFuncSetAttribute(contranorm_main,
                         cudaFuncAttributeMaxDynamicSharedMemorySize, SMEM_TOTAL);
    contranorm_main<<<N_ROWS / BM, 512, SMEM_TOTAL>>>(x, out);
}

// round 3
// speedup vs baseline: 1.1432x; 1.1432x over previous
#include <cuda_runtime.h>
#include <cuda_fp16.h>
#include <cstdint>

// ============================================================================
// ContraNorm: out = 1.1*x - 0.1 * softmax(xn @ xn^T) @ x,   N=16384, D=256
// Flash formulation, mma.sync m16n8k16 (fp16, fp32 accum), cp.async double
// buffering, PV-B via ldmatrix.trans from the K tile (norm folded into P).
// ============================================================================

#define N_ROWS 16384
#define DIM    256
#define BM     128
#define BN     128
#define NTILES (N_ROWS / BN)

__device__ __align__(16) __half g_xn[(size_t)N_ROWS * DIM];  // normalized rows (fp16)
__device__ __align__(16) float  g_norm[N_ROWS];              // row L2 norms

// ---------------------------------------------------------------------------
__device__ __forceinline__ uint32_t smem_to_u32(const void* p) {
    uint32_t a;
    asm("{ .reg .u64 t; cvta.to.shared.u64 t, %1; cvt.u32.u64 %0, t; }" : "=r"(a) : "l"(p));
    return a;
}

__device__ __forceinline__ void ldsm_x4(uint32_t (&r)[4], uint32_t addr) {
    asm volatile("ldmatrix.sync.aligned.m8n8.x4.shared.b16 {%0,%1,%2,%3}, [%4];"
        : "=r"(r[0]), "=r"(r[1]), "=r"(r[2]), "=r"(r[3]) : "r"(addr));
}
__device__ __forceinline__ void ldsm_x4_t(uint32_t (&r)[4], uint32_t addr) {
    asm volatile("ldmatrix.sync.aligned.m8n8.x4.trans.shared.b16 {%0,%1,%2,%3}, [%4];"
        : "=r"(r[0]), "=r"(r[1]), "=r"(r[2]), "=r"(r[3]) : "r"(addr));
}

__device__ __forceinline__ void mma_f16(float (&c)[4], const uint32_t (&a)[4],
                                        uint32_t b0, uint32_t b1) {
    asm volatile(
        "mma.sync.aligned.m16n8k16.row.col.f32.f16.f16.f32 "
        "{%0,%1,%2,%3}, {%4,%5,%6,%7}, {%8,%9}, {%0,%1,%2,%3};"
        : "+f"(c[0]), "+f"(c[1]), "+f"(c[2]), "+f"(c[3])
        : "r"(a[0]), "r"(a[1]), "r"(a[2]), "r"(a[3]), "r"(b0), "r"(b1));
}

#define STS32(smem_addr, v) \
    asm volatile("st.shared.b32 [%0], %1;" :: "r"(smem_addr), "r"(v) : "memory")

#define CP_ASYNC16(dst, src) \
    asm volatile("cp.async.cg.shared.global [%0], [%1], 16;" :: "r"(dst), "l"(src) : "memory")
#define CP_COMMIT() asm volatile("cp.async.commit_group;" ::: "memory")
#define CP_WAIT(n)  asm volatile("cp.async.wait_group %0;" :: "n"(n) : "memory")

// SMEM layout (bytes)
#define SQ  0           // Q tile   [128][256] fp16, row stride 512 B (swizzled)
#define SK0 65536       // K tile buf0
#define SK1 131072      // K tile buf1
#define SP  196608      // P tile [128][128] fp16, row stride 256 B (swizzled)
#define SN  229376      // norms: 2 x 512 B
#define SMEM_TOTAL 230400

// ---------------------------------------------------------------------------
// Prologue: per-row L2 normalize fp32 -> fp16, also store norms
// ---------------------------------------------------------------------------
__global__ void normalize_kernel(const float* __restrict__ x) {
    int row  = blockIdx.x * 8 + (threadIdx.x >> 5);
    int lane = threadIdx.x & 31;
    const float4* xr = reinterpret_cast<const float4*>(x + (size_t)row * DIM);
    float4 a = xr[lane * 2];
    float4 b = xr[lane * 2 + 1];
    float ss = a.x*a.x + a.y*a.y + a.z*a.z + a.w*a.w
             + b.x*b.x + b.y*b.y + b.z*b.z + b.w*b.w;
    #pragma unroll
    for (int o = 16; o > 0; o >>= 1) ss += __shfl_xor_sync(0xFFFFFFFFu, ss, o);
    float nrm = sqrtf(ss);
    float inv = 1.0f / fmaxf(nrm, 1e-12f);

    __half2 p0 = __floats2half2_rn(a.x * inv, a.y * inv);
    __half2 p1 = __floats2half2_rn(a.z * inv, a.w * inv);
    __half2 p2 = __floats2half2_rn(b.x * inv, b.y * inv);
    __half2 p3 = __floats2half2_rn(b.z * inv, b.w * inv);
    uint4 v;
    v.x = *reinterpret_cast<uint32_t*>(&p0);
    v.y = *reinterpret_cast<uint32_t*>(&p1);
    v.z = *reinterpret_cast<uint32_t*>(&p2);
    v.w = *reinterpret_cast<uint32_t*>(&p3);
    *reinterpret_cast<uint4*>(&g_xn[(size_t)row * DIM + lane * 8]) = v;
    if (lane == 0) g_norm[row] = nrm;
}

// ---------------------------------------------------------------------------
// async prefetch of one K tile (+ its 128 norms)
// ---------------------------------------------------------------------------
__device__ __forceinline__ void prefetch_tile(uint32_t sb, int tid, int jt) {
    uint32_t kb = sb + SK0 + ((uint32_t)(jt & 1) << 16);
    const __half* src = g_xn + (size_t)jt * BN * DIM;
    #pragma unroll
    for (int it = 0; it < 8; it++) {
        int idx = tid + it * 512;
        int row = idx >> 5;
        int c16 = idx & 31;
        uint32_t dst = kb + (uint32_t)row * 512 + (((uint32_t)c16 * 16) ^ ((row & 7) << 4));
        CP_ASYNC16(dst, src + row * DIM + c16 * 8);
    }
    if (tid < 32) {
        uint32_t dst = sb + SN + ((uint32_t)(jt & 1) << 9) + (uint32_t)tid * 16;
        CP_ASYNC16(dst, g_norm + jt * BN + tid * 4);
    }
}

// ---------------------------------------------------------------------------
// Main flash kernel: 1 CTA per 128-row block, 512 threads (16 warps, 8x2)
// ---------------------------------------------------------------------------
__global__ void __launch_bounds__(512, 1)
contranorm_main(const float* __restrict__ x, float* __restrict__ out) {
    extern __shared__ __align__(1024) char smem[];
    const uint32_t sb = smem_to_u32(smem);
    const int tid  = threadIdx.x;
    const int lane = tid & 31;
    const int wid  = tid >> 5;
    const int wr   = wid >> 1;            // 0..7 row-warp
    const int wc   = wid & 1;             // 0..1 col-warp
    const int m0   = wr * 16;
    const int keybase = wc * 64;          // S col slice
    const int dimbase = wc * 128;         // O col slice
    const int r0   = blockIdx.x * BM;

    const int sub = lane >> 3;            // ldmatrix submatrix id
    const int li  = lane & 7;
    const uint32_t XR  = (uint32_t)li << 4;         // swizzle term (row&7 == li)
    const uint32_t csA = (uint32_t)((sub >> 1) << 4);
    const uint32_t csB = (uint32_t)((sub & 1) << 4);
    const int rowA = li + ((sub & 1) << 3);         // A-frag rows / PV-B (trans) rows
    const int rowB = li + ((sub >> 1) << 3);        // QK-B rows
    const uint32_t dim2 = (uint32_t)dimbase * 2;

    // thread-constant bases
    const uint32_t a_qk = sb + SQ + (uint32_t)(m0 + rowA) * 512;
    const uint32_t a_pv = sb + SP + (uint32_t)(m0 + rowA) * 256;

    // P store addressing
    const int g4 = lane >> 2;             // 0..7
    const int q4 = lane & 3;              // 0..3
    const uint32_t XRp  = (uint32_t)g4 << 4;
    const uint32_t p_lo = sb + SP + (uint32_t)(m0 + g4) * 256;
    const uint32_t p_hi = p_lo + 8 * 256;

    // ---- async-load Q tile + tile 0 (+norms) as group 0 ----
    {
        const __half* src = g_xn + (size_t)r0 * DIM;
        #pragma unroll
        for (int it = 0; it < 8; it++) {
            int idx = tid + it * 512;
            int row = idx >> 5;
            int c16 = idx & 31;
            uint32_t dst = sb + SQ + (uint32_t)row * 512 + (((uint32_t)c16 * 16) ^ ((row & 7) << 4));
            CP_ASYNC16(dst, src + row * DIM + c16 * 8);
        }
    }
    prefetch_tile(sb, tid, 0);
    CP_COMMIT();

    float oacc[16][4];
    #pragma unroll
    for (int t = 0; t < 16; t++)
        #pragma unroll
        for (int u = 0; u < 4; u++) oacc[t][u] = 0.0f;
    float dsum0 = 0.0f, dsum1 = 0.0f;

    for (int j = 0; j < NTILES; j++) {
        if (j + 1 < NTILES) {
            prefetch_tile(sb, tid, j + 1);
            CP_COMMIT();
            CP_WAIT(1);
        } else {
            CP_WAIT(0);
        }
        __syncthreads();   // tile j visible; previous compute done

        const uint32_t kb = sb + SK0 + ((uint32_t)(j & 1) << 16);

        // ---- QK^T: S[16 x 64] per warp, K=256 ----
        float sacc[8][4];
        #pragma unroll
        for (int t = 0; t < 8; t++)
            #pragma unroll
            for (int u = 0; u < 4; u++) sacc[t][u] = 0.0f;

        const uint32_t b_qk = kb + (uint32_t)(keybase + rowB) * 512;
        #pragma unroll 4
        for (int kk = 0; kk < 16; kk++) {
            uint32_t a[4];
            ldsm_x4(a, a_qk + ((((uint32_t)kk << 5) | csA) ^ XR));
            uint32_t colB = (((uint32_t)kk << 5) | csB) ^ XR;
            #pragma unroll
            for (int q = 0; q < 4; q++) {
                uint32_t b[4];
                ldsm_x4(b, b_qk + (uint32_t)q * 8192 + colB);
                mma_f16(sacc[2 * q],     a, b[0], b[1]);
                mma_f16(sacc[2 * q + 1], a, b[2], b[3]);
            }
        }

        // ---- epilogue: e = exp(S); denom += e; P = e * norm_n (fp16 -> SMEM) ----
        const float* nrm = reinterpret_cast<const float*>(smem + SN + ((j & 1) << 9));
        #pragma unroll
        for (int nt = 0; nt < 8; nt++) {
            int c = keybase + nt * 8 + q4 * 2;
            float2 nn = *reinterpret_cast<const float2*>(nrm + c);
            float e0 = __expf(sacc[nt][0]);
            float e1 = __expf(sacc[nt][1]);
            float e2 = __expf(sacc[nt][2]);
            float e3 = __expf(sacc[nt][3]);
            dsum0 += e0 + e1;
            dsum1 += e2 + e3;
            __half2 plo = __floats2half2_rn(e0 * nn.x, e1 * nn.y);
            __half2 phi = __floats2half2_rn(e2 * nn.x, e3 * nn.y);
            uint32_t colb = ((uint32_t)c * 2) ^ XRp;
            STS32(p_lo + colb, *reinterpret_cast<uint32_t*>(&plo));
            STS32(p_hi + colb, *reinterpret_cast<uint32_t*>(&phi));
        }
        __syncthreads();   // P complete

        // ---- PV: O[16 x 128] per warp += P @ V  (B via ldmatrix.trans of K tile) ----
        const uint32_t b_pv = kb + (uint32_t)rowA * 512;
        #pragma unroll 2
        for (int kk = 0; kk < 8; kk++) {
            uint32_t a[4];
            ldsm_x4(a, a_pv + ((((uint32_t)kk << 5) | csA) ^ XR));
            uint32_t rbase = b_pv + (uint32_t)kk * 8192;
            #pragma unroll
            for (int q = 0; q < 8; q++) {
                uint32_t b[4];
                ldsm_x4_t(b, rbase + ((dim2 + ((uint32_t)q << 5) + csA) ^ XR));
                mma_f16(oacc[2 * q],     a, b[0], b[1]);
                mma_f16(oacc[2 * q + 1], a, b[2], b[3]);
            }
        }
        __syncthreads();   // done reading buf[j&1] and P
    }

    // ---- cross-warp denominator reduction (each warp-pair summed 64 cols) ----
    float d0 = dsum0, d1 = dsum1;
    d0 += __shfl_xor_sync(0xFFFFFFFFu, d0, 1);
    d0 += __shfl_xor_sync(0xFFFFFFFFu, d0, 2);
    d1 += __shfl_xor_sync(0xFFFFFFFFu, d1, 1);
    d1 += __shfl_xor_sync(0xFFFFFFFFu, d1, 2);
    float* sd = reinterpret_cast<float*>(smem + SP);   // reuse P region
    if (q4 == 0) {
        sd[(m0 + g4) * 2 + wc]     = d0;
        sd[(m0 + g4 + 8) * 2 + wc] = d1;
    }
    __syncthreads();
    float den_lo = sd[(m0 + g4) * 2]     + sd[(m0 + g4) * 2 + 1];
    float den_hi = sd[(m0 + g4 + 8) * 2] + sd[(m0 + g4 + 8) * 2 + 1];

    // ---- final blend: out = 1.1*x - (0.1/denom) * O ----
    {
        float c0 = 0.1f / den_lo;
        float c1 = 0.1f / den_hi;
        int row_lo = r0 + m0 + g4;
        int row_hi = row_lo + 8;
        const float2* x_lo = reinterpret_cast<const float2*>(x + (size_t)row_lo * DIM);
        const float2* x_hi = reinterpret_cast<const float2*>(x + (size_t)row_hi * DIM);
        float2* o_lo = reinterpret_cast<float2*>(out + (size_t)row_lo * DIM);
        float2* o_hi = reinterpret_cast<float2*>(out + (size_t)row_hi * DIM);
        #pragma unroll
        for (int nt = 0; nt < 16; nt++) {
            int cidx = (dimbase + nt * 8 + q4 * 2) >> 1;
            float2 xv = x_lo[cidx];
            float2 ov;
            ov.x = 1.1f * xv.x - c0 * oacc[nt][0];
            ov.y = 1.1f * xv.y - c0 * oacc[nt][1];
            o_lo[cidx] = ov;
            float2 xw = x_hi[cidx];
            float2 ow;
            ow.x = 1.1f * xw.x - c1 * oacc[nt][2];
            ow.y = 1.1f * xw.y - c1 * oacc[nt][3];
            o_hi[cidx] = ow;
        }
    }
}

// ---------------------------------------------------------------------------
extern "C" void kernel_launch(void* const* d_in, const int* in_sizes, int n_in,
                              void* d_out, int out_size) {
    const float* x = (const float*)d_in[0];
    float* out = (float*)d_out;

    normalize_kernel<<<N_ROWS / 8, 256>>>(x);

    cudaFuncSetAttribute(contranorm_main,
                         cudaFuncAttributeMaxDynamicSharedMemorySize, SMEM_TOTAL);
    contranorm_main<<<N_ROWS / BM, 512, SMEM_TOTAL>>>(x, out);
}

// round 4
// speedup vs baseline: 1.1982x; 1.0482x over previous
#include <cuda_runtime.h>
#include <cuda_fp16.h>
#include <cstdint>

// ============================================================================
// ContraNorm: out = 1.1*x - 0.1 * softmax(xn @ xn^T) @ x,   N=16384, D=256
// Flash formulation, mma.sync m16n8k16 (fp16, fp32 accum), cp.async double
// buffering. 4x4 warp grid (32x32 S tiles / 32x64 O tiles) for ldsm reuse;
// own-key PV A-fragments come straight from registers (C->A identity).
// ============================================================================

#define N_ROWS 16384
#define DIM    256
#define BM     128
#define BN     128
#define NTILES (N_ROWS / BN)

__device__ __align__(16) __half g_xn[(size_t)N_ROWS * DIM];  // normalized rows (fp16)
__device__ __align__(16) float  g_norm[N_ROWS];              // row L2 norms

// ---------------------------------------------------------------------------
__device__ __forceinline__ uint32_t smem_to_u32(const void* p) {
    uint32_t a;
    asm("{ .reg .u64 t; cvta.to.shared.u64 t, %1; cvt.u32.u64 %0, t; }" : "=r"(a) : "l"(p));
    return a;
}

__device__ __forceinline__ void ldsm_x4(uint32_t (&r)[4], uint32_t addr) {
    asm volatile("ldmatrix.sync.aligned.m8n8.x4.shared.b16 {%0,%1,%2,%3}, [%4];"
        : "=r"(r[0]), "=r"(r[1]), "=r"(r[2]), "=r"(r[3]) : "r"(addr));
}
__device__ __forceinline__ void ldsm_x4_t(uint32_t (&r)[4], uint32_t addr) {
    asm volatile("ldmatrix.sync.aligned.m8n8.x4.trans.shared.b16 {%0,%1,%2,%3}, [%4];"
        : "=r"(r[0]), "=r"(r[1]), "=r"(r[2]), "=r"(r[3]) : "r"(addr));
}

__device__ __forceinline__ void mma_f16(float (&c)[4], const uint32_t (&a)[4],
                                        uint32_t b0, uint32_t b1) {
    asm volatile(
        "mma.sync.aligned.m16n8k16.row.col.f32.f16.f16.f32 "
        "{%0,%1,%2,%3}, {%4,%5,%6,%7}, {%8,%9}, {%0,%1,%2,%3};"
        : "+f"(c[0]), "+f"(c[1]), "+f"(c[2]), "+f"(c[3])
        : "r"(a[0]), "r"(a[1]), "r"(a[2]), "r"(a[3]), "r"(b0), "r"(b1));
}

#define STS32(smem_addr, v) \
    asm volatile("st.shared.b32 [%0], %1;" :: "r"(smem_addr), "r"(v) : "memory")

#define CP_ASYNC16(dst, src) \
    asm volatile("cp.async.cg.shared.global [%0], [%1], 16;" :: "r"(dst), "l"(src) : "memory")
#define CP_COMMIT() asm volatile("cp.async.commit_group;" ::: "memory")
#define CP_WAIT(n)  asm volatile("cp.async.wait_group %0;" :: "n"(n) : "memory")

// SMEM layout (bytes)
#define SQ  0           // Q tile   [128][256] fp16, row stride 512 B (swizzled)
#define SK0 65536       // K tile buf0
#define SK1 131072      // K tile buf1
#define SP  196608      // P tile [128][128] fp16, row stride 256 B (swizzled)
#define SN  229376      // norms: 2 x 512 B
#define SMEM_TOTAL 230400

// ---------------------------------------------------------------------------
// Prologue: per-row L2 normalize fp32 -> fp16, also store norms
// ---------------------------------------------------------------------------
__global__ void normalize_kernel(const float* __restrict__ x) {
    int row  = blockIdx.x * 8 + (threadIdx.x >> 5);
    int lane = threadIdx.x & 31;
    const float4* xr = reinterpret_cast<const float4*>(x + (size_t)row * DIM);
    float4 a = xr[lane * 2];
    float4 b = xr[lane * 2 + 1];
    float ss = a.x*a.x + a.y*a.y + a.z*a.z + a.w*a.w
             + b.x*b.x + b.y*b.y + b.z*b.z + b.w*b.w;
    #pragma unroll
    for (int o = 16; o > 0; o >>= 1) ss += __shfl_xor_sync(0xFFFFFFFFu, ss, o);
    float nrm = sqrtf(ss);
    float inv = 1.0f / fmaxf(nrm, 1e-12f);

    __half2 p0 = __floats2half2_rn(a.x * inv, a.y * inv);
    __half2 p1 = __floats2half2_rn(a.z * inv, a.w * inv);
    __half2 p2 = __floats2half2_rn(b.x * inv, b.y * inv);
    __half2 p3 = __floats2half2_rn(b.z * inv, b.w * inv);
    uint4 v;
    v.x = *reinterpret_cast<uint32_t*>(&p0);
    v.y = *reinterpret_cast<uint32_t*>(&p1);
    v.z = *reinterpret_cast<uint32_t*>(&p2);
    v.w = *reinterpret_cast<uint32_t*>(&p3);
    *reinterpret_cast<uint4*>(&g_xn[(size_t)row * DIM + lane * 8]) = v;
    if (lane == 0) g_norm[row] = nrm;
}

// ---------------------------------------------------------------------------
// async prefetch of one K tile (+ its 128 norms)
// ---------------------------------------------------------------------------
__device__ __forceinline__ void prefetch_tile(uint32_t sb, int tid, int jt) {
    uint32_t kb = sb + SK0 + ((uint32_t)(jt & 1) << 16);
    const __half* src = g_xn + (size_t)jt * BN * DIM;
    #pragma unroll
    for (int it = 0; it < 8; it++) {
        int idx = tid + it * 512;
        int row = idx >> 5;
        int c16 = idx & 31;
        uint32_t dst = kb + (uint32_t)row * 512 + (((uint32_t)c16 * 16) ^ ((row & 7) << 4));
        CP_ASYNC16(dst, src + row * DIM + c16 * 8);
    }
    if (tid < 32) {
        uint32_t dst = sb + SN + ((uint32_t)(jt & 1) << 9) + (uint32_t)tid * 16;
        CP_ASYNC16(dst, g_norm + jt * BN + tid * 4);
    }
}

// ---------------------------------------------------------------------------
// Main flash kernel: 1 CTA per 128-row block, 512 threads (16 warps, 4x4)
// ---------------------------------------------------------------------------
__global__ void __launch_bounds__(512, 1)
contranorm_main(const float* __restrict__ x, float* __restrict__ out) {
    extern __shared__ __align__(1024) char smem[];
    const uint32_t sb = smem_to_u32(smem);
    const int tid  = threadIdx.x;
    const int lane = tid & 31;
    const int wid  = tid >> 5;
    const int mi   = wid >> 2;            // 0..3 row-warp
    const int ni   = wid & 3;             // 0..3 col-warp
    const int m0   = mi * 32;             // S/O row base
    const int n0   = ni * 32;             // S col base (keys)
    const int d0   = ni * 64;             // O col base (dims)
    const int r0   = blockIdx.x * BM;

    const int sub = lane >> 3;            // ldmatrix submatrix id
    const int li  = lane & 7;
    const uint32_t XR  = (uint32_t)li << 4;
    const uint32_t csA = (uint32_t)((sub >> 1) << 4);
    const uint32_t csB = (uint32_t)((sub & 1) << 4);
    const int rowA = li + ((sub & 1) << 3);
    const int rowB = li + ((sub >> 1) << 3);
    const uint32_t d02 = (uint32_t)d0 * 2;

    // thread-constant bases
    const uint32_t a_qk = sb + SQ + (uint32_t)(m0 + rowA) * 512;
    const uint32_t a_pv = sb + SP + (uint32_t)(m0 + rowA) * 256;

    // P store / output addressing
    const int g4 = lane >> 2;             // 0..7
    const int q4 = lane & 3;              // 0..3
    const uint32_t XRp  = (uint32_t)g4 << 4;
    // row base for (ma, lo): SP + (m0 + ma*16 + g4)*256 ; hi adds 8*256
    const uint32_t p_st0 = sb + SP + (uint32_t)(m0 + g4) * 256;

    // ---- async-load Q tile + tile 0 (+norms) as group 0 ----
    {
        const __half* src = g_xn + (size_t)r0 * DIM;
        #pragma unroll
        for (int it = 0; it < 8; it++) {
            int idx = tid + it * 512;
            int row = idx >> 5;
            int c16 = idx & 31;
            uint32_t dst = sb + SQ + (uint32_t)row * 512 + (((uint32_t)c16 * 16) ^ ((row & 7) << 4));
            CP_ASYNC16(dst, src + row * DIM + c16 * 8);
        }
    }
    prefetch_tile(sb, tid, 0);
    CP_COMMIT();

    float oacc[16][4];                     // [ma*8 + q*2 + j][4]
    #pragma unroll
    for (int t = 0; t < 16; t++)
        #pragma unroll
        for (int u = 0; u < 4; u++) oacc[t][u] = 0.0f;
    float dsum[2][2] = {{0.0f, 0.0f}, {0.0f, 0.0f}};   // [ma][lo/hi]

    for (int j = 0; j < NTILES; j++) {
        if (j + 1 < NTILES) {
            prefetch_tile(sb, tid, j + 1);
            CP_COMMIT();
            CP_WAIT(1);
        } else {
            CP_WAIT(0);
        }
        __syncthreads();   // tile j visible; previous compute done

        const uint32_t kb = sb + SK0 + ((uint32_t)(j & 1) << 16);

        // ---- QK^T: S[32 x 32] per warp, K=256 ----
        float sacc[8][4];                  // [ma*4 + nb][4]
        #pragma unroll
        for (int t = 0; t < 8; t++)
            #pragma unroll
            for (int u = 0; u < 4; u++) sacc[t][u] = 0.0f;

        const uint32_t b_qk = kb + (uint32_t)(n0 + rowB) * 512;
        #pragma unroll
        for (int kk = 0; kk < 16; kk++) {
            uint32_t colA = (((uint32_t)kk << 5) | csA) ^ XR;
            uint32_t colB = (((uint32_t)kk << 5) | csB) ^ XR;
            uint32_t a0[4], a1[4];
            ldsm_x4(a0, a_qk + colA);
            ldsm_x4(a1, a_qk + 8192 + colA);
            #pragma unroll
            for (int nb2 = 0; nb2 < 2; nb2++) {
                uint32_t b[4];
                ldsm_x4(b, b_qk + (uint32_t)nb2 * 8192 + colB);
                mma_f16(sacc[nb2 * 2],     a0, b[0], b[1]);
                mma_f16(sacc[nb2 * 2 + 1], a0, b[2], b[3]);
                mma_f16(sacc[4 + nb2 * 2],     a1, b[0], b[1]);
                mma_f16(sacc[4 + nb2 * 2 + 1], a1, b[2], b[3]);
            }
        }

        // ---- epilogue: e = exp(S); denom += e; P = e*norm_n -> SMEM + regs ----
        const float* nrm = reinterpret_cast<const float*>(smem + SN + ((j & 1) << 9));
        uint32_t pa[2][4][2];              // [ma][nb][lo/hi] half2 fragments
        #pragma unroll
        for (int ma = 0; ma < 2; ma++) {
            #pragma unroll
            for (int nb = 0; nb < 4; nb++) {
                int c = n0 + nb * 8 + q4 * 2;
                float2 nn = *reinterpret_cast<const float2*>(nrm + c);
                float e0 = __expf(sacc[ma * 4 + nb][0]);
                float e1 = __expf(sacc[ma * 4 + nb][1]);
                float e2 = __expf(sacc[ma * 4 + nb][2]);
                float e3 = __expf(sacc[ma * 4 + nb][3]);
                dsum[ma][0] += e0 + e1;
                dsum[ma][1] += e2 + e3;
                __half2 plo = __floats2half2_rn(e0 * nn.x, e1 * nn.y);
                __half2 phi = __floats2half2_rn(e2 * nn.x, e3 * nn.y);
                uint32_t ulo = *reinterpret_cast<uint32_t*>(&plo);
                uint32_t uhi = *reinterpret_cast<uint32_t*>(&phi);
                pa[ma][nb][0] = ulo;
                pa[ma][nb][1] = uhi;
                uint32_t addr = p_st0 + (uint32_t)ma * 4096 + (((uint32_t)c * 2) ^ XRp);
                STS32(addr, ulo);
                STS32(addr + 2048, uhi);
            }
        }
        __syncthreads();   // P complete

        // ---- PV: O[32 x 64] per warp += P @ V  (B via ldmatrix.trans of K tile) ----
        const uint32_t b_pv = kb + (uint32_t)rowA * 512;
        #pragma unroll
        for (int kk = 0; kk < 8; kk++) {
            uint32_t a0[4], a1[4];
            if ((kk >> 1) == ni) {
                int t2 = (kk & 1) * 2;
                a0[0] = pa[0][t2][0]; a0[1] = pa[0][t2][1];
                a0[2] = pa[0][t2 + 1][0]; a0[3] = pa[0][t2 + 1][1];
                a1[0] = pa[1][t2][0]; a1[1] = pa[1][t2][1];
                a1[2] = pa[1][t2 + 1][0]; a1[3] = pa[1][t2 + 1][1];
            } else {
                uint32_t colA = (((uint32_t)kk << 5) | csA) ^ XR;
                ldsm_x4(a0, a_pv + colA);
                ldsm_x4(a1, a_pv + 4096 + colA);
            }
            uint32_t rbase = b_pv + (uint32_t)kk * 8192;
            #pragma unroll
            for (int q = 0; q < 4; q++) {
                uint32_t b[4];
                ldsm_x4_t(b, rbase + ((d02 + ((uint32_t)q << 5) + csA) ^ XR));
                mma_f16(oacc[q * 2],     a0, b[0], b[1]);
                mma_f16(oacc[q * 2 + 1], a0, b[2], b[3]);
                mma_f16(oacc[8 + q * 2],     a1, b[0], b[1]);
                mma_f16(oacc[8 + q * 2 + 1], a1, b[2], b[3]);
            }
        }
        __syncthreads();   // done reading buf[j&1] and P
    }

    // ---- cross-warp denominator reduction (each warp summed 32 cols) ----
    float* sd = reinterpret_cast<float*>(smem + SP);   // reuse P region: [128][4]
    #pragma unroll
    for (int ma = 0; ma < 2; ma++) {
        #pragma unroll
        for (int lh = 0; lh < 2; lh++) {
            float d = dsum[ma][lh];
            d += __shfl_xor_sync(0xFFFFFFFFu, d, 1);
            d += __shfl_xor_sync(0xFFFFFFFFu, d, 2);
            if (q4 == 0) sd[(m0 + ma * 16 + lh * 8 + g4) * 4 + ni] = d;
        }
    }
    __syncthreads();

    // ---- final blend: out = 1.1*x - (0.1/denom) * O ----
    #pragma unroll
    for (int ma = 0; ma < 2; ma++) {
        int rl = m0 + ma * 16 + g4;
        int rh = rl + 8;
        float dl = sd[rl * 4] + sd[rl * 4 + 1] + sd[rl * 4 + 2] + sd[rl * 4 + 3];
        float dh = sd[rh * 4] + sd[rh * 4 + 1] + sd[rh * 4 + 2] + sd[rh * 4 + 3];
        float cl = 0.1f / dl;
        float ch = 0.1f / dh;
        const float2* x_lo = reinterpret_cast<const float2*>(x + (size_t)(r0 + rl) * DIM);
        const float2* x_hi = reinterpret_cast<const float2*>(x + (size_t)(r0 + rh) * DIM);
        float2* o_lo = reinterpret_cast<float2*>(out + (size_t)(r0 + rl) * DIM);
        float2* o_hi = reinterpret_cast<float2*>(out + (size_t)(r0 + rh) * DIM);
        #pragma unroll
        for (int q = 0; q < 4; q++) {
            #pragma unroll
            for (int jj = 0; jj < 2; jj++) {
                int cidx = (d0 + q * 16 + jj * 8 + q4 * 2) >> 1;
                const float* o4 = oacc[ma * 8 + q * 2 + jj];
                float2 xv = x_lo[cidx];
                float2 ov;
                ov.x = 1.1f * xv.x - cl * o4[0];
                ov.y = 1.1f * xv.y - cl * o4[1];
                o_lo[cidx] = ov;
                float2 xw = x_hi[cidx];
                float2 ow;
                ow.x = 1.1f * xw.x - ch * o4[2];
                ow.y = 1.1f * xw.y - ch * o4[3];
                o_hi[cidx] = ow;
            }
        }
    }
}

// ---------------------------------------------------------------------------
extern "C" void kernel_launch(void* const* d_in, const int* in_sizes, int n_in,
                              void* d_out, int out_size) {
    const float* x = (const float*)d_in[0];
    float* out = (float*)d_out;

    normalize_kernel<<<N_ROWS / 8, 256>>>(x);

    cudaFuncSetAttribute(contranorm_main,
                         cudaFuncAttributeMaxDynamicSharedMemorySize, SMEM_TOTAL);
    contranorm_main<<<N_ROWS / BM, 512, SMEM_TOTAL>>>(x, out);
}